// round 3
// baseline (speedup 1.0000x reference)
#include <cuda_runtime.h>
#include <cuda_bf16.h>
#include <cstdint>

// Problem constants
#define BB 2
#define SS 2048
#define DD 1024
#define HH 16
#define DH 64          // head dim (= dvh)
#define NQK 2048       // Wqk output cols
#define NTOT 3072      // 2048 (qk) + 1024 (v)

// Scratch: q/k/v in [B, H, S, DH] layout. 3 x 16 MB.
__device__ float g_q[BB * HH * SS * DH];
__device__ float g_k[BB * HH * SS * DH];
__device__ float g_v[BB * HH * SS * DH];

// ---------------------------------------------------------------------------
// Kernel 1: fused QKV projection GEMM with scatter epilogue.
// C[M=4096, N=3072] = x[4096,1024] @ [Wqk | Wv] + [bqk | bv]
// Block tile 64x64, K-step 16, 256 threads, 4x4 micro-tile per thread.
// q is pre-scaled by 1/sqrt(64) = 0.125 in the epilogue.
// ---------------------------------------------------------------------------
__global__ __launch_bounds__(256) void qkv_gemm_kernel(
    const float* __restrict__ x,
    const float* __restrict__ Wqk,
    const float* __restrict__ bqk,
    const float* __restrict__ Wv,
    const float* __restrict__ bv)
{
    __shared__ float As[16][64];   // A^T tile: As[k][m]
    __shared__ float Ws[16][64];   // W tile:   Ws[k][n]

    const int bm = blockIdx.y;          // 0..63
    const int bn = blockIdx.x;          // 0..47
    const int n0 = bn * 64;

    const float* W;
    const float* bias;
    int ldw, ncol0;
    if (n0 < NQK) { W = Wqk; ldw = NQK; bias = bqk; ncol0 = n0; }
    else          { W = Wv;  ldw = DD;  bias = bv;  ncol0 = n0 - NQK; }

    const int tid = threadIdx.x;
    const int tx = tid & 15;            // 0..15 (N dir)
    const int ty = tid >> 4;            // 0..15 (M dir)

    float acc[4][4];
#pragma unroll
    for (int i = 0; i < 4; i++)
#pragma unroll
        for (int j = 0; j < 4; j++) acc[i][j] = 0.f;

    // preload addresses
    const int a_m  = tid >> 2;          // 0..63
    const int a_kk = (tid & 3) * 4;     // 0,4,8,12
    const int w_kk = tid >> 4;          // 0..15
    const int w_n  = (tid & 15) * 4;    // 0..60

    for (int k0 = 0; k0 < DD; k0 += 16) {
        // load A tile (64 x 16) transposed
        {
            float4 a = *(const float4*)&x[(size_t)(bm * 64 + a_m) * DD + k0 + a_kk];
            As[a_kk + 0][a_m] = a.x;
            As[a_kk + 1][a_m] = a.y;
            As[a_kk + 2][a_m] = a.z;
            As[a_kk + 3][a_m] = a.w;
        }
        // load W tile (16 x 64)
        {
            float4 w = *(const float4*)&W[(size_t)(k0 + w_kk) * ldw + ncol0 + w_n];
            *(float4*)&Ws[w_kk][w_n] = w;
        }
        __syncthreads();

#pragma unroll
        for (int kk = 0; kk < 16; kk++) {
            float4 ra = *(const float4*)&As[kk][ty * 4];
            float4 rb = *(const float4*)&Ws[kk][tx * 4];
            float a0 = ra.x, a1 = ra.y, a2 = ra.z, a3 = ra.w;
            float b0 = rb.x, b1 = rb.y, b2 = rb.z, b3 = rb.w;
            acc[0][0] += a0 * b0; acc[0][1] += a0 * b1; acc[0][2] += a0 * b2; acc[0][3] += a0 * b3;
            acc[1][0] += a1 * b0; acc[1][1] += a1 * b1; acc[1][2] += a1 * b2; acc[1][3] += a1 * b3;
            acc[2][0] += a2 * b0; acc[2][1] += a2 * b1; acc[2][2] += a2 * b2; acc[2][3] += a2 * b3;
            acc[3][0] += a3 * b0; acc[3][1] += a3 * b1; acc[3][2] += a3 * b2; acc[3][3] += a3 * b3;
        }
        __syncthreads();
    }

    // epilogue: bias, scatter to q/k/v [B,H,S,DH], q scaled by 0.125
#pragma unroll
    for (int i = 0; i < 4; i++) {
        const int m  = bm * 64 + ty * 4 + i;
        const int b  = m >> 11;          // / SS
        const int s  = m & (SS - 1);
#pragma unroll
        for (int j = 0; j < 4; j++) {
            const int n = n0 + tx * 4 + j;
            float val = acc[i][j] + bias[ncol0 + tx * 4 + j];
            float* dst;
            int nn;
            if (n < DD)            { dst = g_q; nn = n;        val *= 0.125f; }
            else if (n < NQK)      { dst = g_k; nn = n - DD;   }
            else                   { dst = g_v; nn = n - NQK;  }
            const int h  = nn >> 6;
            const int dd = nn & 63;
            dst[(((size_t)(b * HH + h)) * SS + s) * DH + dd] = val;
        }
    }
}

// ---------------------------------------------------------------------------
// Kernel 2: causal flash attention, fp32.
// One block = 128 query rows of one (b, h). One thread = one query row.
// K/V tiles of 32 rows staged in smem. Q tile in smem (stride 68, padded).
// Online softmax in registers: s[32], o[64].
// ---------------------------------------------------------------------------
#define QT 128
#define KT 32
#define QPAD 68

__global__ __launch_bounds__(QT) void attn_kernel(float* __restrict__ out)
{
    extern __shared__ float sm[];
    float (*Qs)[QPAD] = (float (*)[QPAD])sm;                 // [QT][68]
    float (*Ks)[DH]   = (float (*)[DH])(sm + QT * QPAD);     // [KT][64]
    float (*Vs)[DH]   = (float (*)[DH])(sm + QT * QPAD + KT * DH);

    const int qt = blockIdx.x;    // 0..15
    const int h  = blockIdx.y;    // 0..15
    const int b  = blockIdx.z;    // 0..1
    const int tid = threadIdx.x;  // 0..127

    const size_t head_off = ((size_t)(b * HH + h)) * SS * DH;
    const float* qbase = g_q + head_off;
    const float* kbase = g_k + head_off;
    const float* vbase = g_v + head_off;

    const int q0 = qt * QT;
    const int qi = q0 + tid;

    // load Q tile: 128 rows x 64 = 2048 float4; 16 per thread
#pragma unroll
    for (int it = 0; it < 16; it++) {
        const int idx = tid + it * QT;        // 0..2047
        const int r = idx >> 4;               // /16 float4 per row
        const int c = (idx & 15) * 4;
        float4 v4 = *(const float4*)&qbase[(size_t)(q0 + r) * DH + c];
        *(float4*)&Qs[r][c] = v4;
    }

    float o[DH];
#pragma unroll
    for (int d = 0; d < DH; d++) o[d] = 0.f;
    float mrun = -1e30f, lrun = 0.f;

    const int ktiles = (q0 + QT) / KT;        // causal bound: 4*qt + 4

    for (int kt = 0; kt < ktiles; kt++) {
        const int k0 = kt * KT;
        __syncthreads();   // protect Ks/Vs from previous iteration readers
        // load K,V tiles: 32x64 = 512 float4 each; 4 per thread per tile
#pragma unroll
        for (int it = 0; it < 4; it++) {
            const int idx = tid + it * QT;    // 0..511
            const int r = idx >> 4;
            const int c = (idx & 15) * 4;
            *(float4*)&Ks[r][c] = *(const float4*)&kbase[(size_t)(k0 + r) * DH + c];
            *(float4*)&Vs[r][c] = *(const float4*)&vbase[(size_t)(k0 + r) * DH + c];
        }
        __syncthreads();

        // s[j] = q_row . k_j  (q pre-scaled by 1/8)
        float s[KT];
#pragma unroll
        for (int j = 0; j < KT; j++) s[j] = 0.f;

#pragma unroll
        for (int c = 0; c < 4; c++) {
            float qc[16];
#pragma unroll
            for (int i = 0; i < 16; i += 4) {
                float4 t = *(const float4*)&Qs[tid][c * 16 + i];
                qc[i] = t.x; qc[i + 1] = t.y; qc[i + 2] = t.z; qc[i + 3] = t.w;
            }
#pragma unroll
            for (int j = 0; j < KT; j++) {
#pragma unroll
                for (int i = 0; i < 16; i += 4) {
                    float4 kv = *(const float4*)&Ks[j][c * 16 + i];
                    s[j] += qc[i] * kv.x + qc[i + 1] * kv.y
                          + qc[i + 2] * kv.z + qc[i + 3] * kv.w;
                }
            }
        }

        // causal mask (only the partially-valid tiles need it)
        if (k0 + KT - 1 > qi) {
#pragma unroll
            for (int j = 0; j < KT; j++)
                if (k0 + j > qi) s[j] = -1e30f;
        }

        // online softmax update
        float tmax = -1e30f;
#pragma unroll
        for (int j = 0; j < KT; j++) tmax = fmaxf(tmax, s[j]);
        const float newm = fmaxf(mrun, tmax);
        const float corr = __expf(mrun - newm);
        lrun *= corr;
#pragma unroll
        for (int d = 0; d < DH; d++) o[d] *= corr;

#pragma unroll
        for (int j = 0; j < KT; j++) {
            const float p = __expf(s[j] - newm);
            lrun += p;
#pragma unroll
            for (int d = 0; d < DH; d += 4) {
                float4 vv = *(const float4*)&Vs[j][d];
                o[d]     += p * vv.x;
                o[d + 1] += p * vv.y;
                o[d + 2] += p * vv.z;
                o[d + 3] += p * vv.w;
            }
        }
        mrun = newm;
    }

    // write out[b, qi, h*64 + d]
    const float inv = 1.f / lrun;
    float* op = out + ((size_t)(b * SS + qi)) * (HH * DH) + (size_t)h * DH;
#pragma unroll
    for (int d = 0; d < DH; d += 4) {
        float4 r;
        r.x = o[d] * inv; r.y = o[d + 1] * inv;
        r.z = o[d + 2] * inv; r.w = o[d + 3] * inv;
        *(float4*)&op[d] = r;
    }
}

// ---------------------------------------------------------------------------
extern "C" void kernel_launch(void* const* d_in, const int* in_sizes, int n_in,
                              void* d_out, int out_size)
{
    const float* x   = (const float*)d_in[0];
    const float* Wqk = (const float*)d_in[1];
    const float* bqk = (const float*)d_in[2];
    const float* Wv  = (const float*)d_in[3];
    const float* bv  = (const float*)d_in[4];
    float* out = (float*)d_out;

    // GEMM: grid (N/64, M/64) = (48, 64)
    dim3 g1(NTOT / 64, (BB * SS) / 64);
    qkv_gemm_kernel<<<g1, 256>>>(x, Wqk, bqk, Wv, bv);

    // Attention: dynamic smem (Q padded) = (128*68 + 2*32*64) * 4 = 51200 B
    const int smem_bytes = (QT * QPAD + 2 * KT * DH) * sizeof(float);
    cudaFuncSetAttribute(attn_kernel, cudaFuncAttributeMaxDynamicSharedMemorySize,
                         smem_bytes);
    dim3 g2(SS / QT, HH, BB);
    attn_kernel<<<g2, QT, smem_bytes>>>(out);
}

// round 4
// speedup vs baseline: 1.6905x; 1.6905x over previous
#include <cuda_runtime.h>
#include <cuda_bf16.h>
#include <cstdint>

// Problem constants
#define BB 2
#define SS 2048
#define DD 1024
#define HH 16
#define DH 64
#define NQK 2048       // Wqk output cols (q|k)
#define NTOT 3072      // + 1024 (v)

// Scratch: q/k/v in [B, H, S, DH] layout (q pre-scaled by 1/8).
__device__ float g_q[BB * HH * SS * DH];
__device__ float g_k[BB * HH * SS * DH];
__device__ float g_v[BB * HH * SS * DH];

// ---------------------------------------------------------------------------
// helpers
// ---------------------------------------------------------------------------
__device__ __forceinline__ uint32_t f2tf32(float x) {
    uint32_t r;
    asm("cvt.rna.tf32.f32 %0, %1;" : "=r"(r) : "f"(x));
    return r;
}

__device__ __forceinline__ void mma_tf32(float c[4],
                                         uint32_t a0, uint32_t a1, uint32_t a2, uint32_t a3,
                                         uint32_t b0, uint32_t b1) {
    asm volatile(
        "mma.sync.aligned.m16n8k8.row.col.f32.tf32.tf32.f32 "
        "{%0,%1,%2,%3}, {%4,%5,%6,%7}, {%8,%9}, {%0,%1,%2,%3};"
        : "+f"(c[0]), "+f"(c[1]), "+f"(c[2]), "+f"(c[3])
        : "r"(a0), "r"(a1), "r"(a2), "r"(a3), "r"(b0), "r"(b1));
}

// Fragment-permuted smem index helpers (m16n8k8 tf32 layouts):
// A frag (16x8): a0=(r,c) a1=(r+8,c) a2=(r,c+4) a3=(r+8,c+4), r=lane/4, c=lane%4
// B frag (8x8):  b0=(k,n) b1=(k+4,n), n=lane/4, k=lane%4
// C frag (16x8): c0=(r,2t) c1=(r,2t+1) c2=(r+8,2t) c3=(r+8,2t+1)

// ---------------------------------------------------------------------------
// Kernel 1: QKV projection GEMM, tf32 mma.
// C[4096, 3072] = x[4096,1024] @ [Wqk | Wv] + bias, scatter to g_q/g_k/g_v.
// Block 128x128, K-step 32, 256 threads (8 warps, 2x4), warp tile 64x32.
// ---------------------------------------------------------------------------
__global__ __launch_bounds__(256) void qkv_gemm_tf32(
    const float* __restrict__ x,
    const float* __restrict__ Wqk,
    const float* __restrict__ bqk,
    const float* __restrict__ Wv,
    const float* __restrict__ bv)
{
    // Permuted fragment layout: As[kk(4)][mt(8)][lane(32)][slot(4)], Bs[kk(4)][nt(16)][lane(32)][slot(2)]
    __shared__ float As[4 * 8 * 32 * 4];    // 16 KB
    __shared__ float Bs[4 * 16 * 32 * 2];   // 16 KB

    const int bm = blockIdx.y;
    const int bn = blockIdx.x;
    const int n0 = bn * 128;

    const float* W;
    const float* bias;
    int ldw, ncol0;
    if (n0 < NQK) { W = Wqk; ldw = NQK; bias = bqk; ncol0 = n0; }
    else          { W = Wv;  ldw = DD;  bias = bv;  ncol0 = n0 - NQK; }

    float* dst;
    float scale;
    int sub;
    if (n0 < DD)       { dst = g_q; scale = 0.125f; sub = 0; }
    else if (n0 < NQK) { dst = g_k; scale = 1.f;    sub = DD; }
    else               { dst = g_v; scale = 1.f;    sub = NQK; }

    const int tid  = threadIdx.x;
    const int warp = tid >> 5, lane = tid & 31;
    const int wm = warp >> 2, wn = warp & 3;     // 2 x 4 warp grid
    const int gid = lane >> 2, tig = lane & 3;

    float c[4][4][4];
#pragma unroll
    for (int i = 0; i < 4; i++)
#pragma unroll
        for (int j = 0; j < 4; j++)
#pragma unroll
            for (int s = 0; s < 4; s++) c[i][j][s] = 0.f;

    for (int k0 = 0; k0 < DD; k0 += 32) {
        float4 av[4], bv4[4];
#pragma unroll
        for (int i = 0; i < 4; i++) {
            const int f = tid + i * 256;
            const int r = f >> 3, c4 = f & 7;        // A: 128 rows x 8 float4
            av[i] = *(const float4*)&x[(size_t)(bm * 128 + r) * DD + k0 + c4 * 4];
            const int kr = f >> 5, cb4 = f & 31;     // B: 32 rows x 32 float4
            bv4[i] = *(const float4*)&W[(size_t)(k0 + kr) * ldw + ncol0 + cb4 * 4];
        }
        __syncthreads();   // previous compute done reading smem
#pragma unroll
        for (int i = 0; i < 4; i++) {
            const int f = tid + i * 256;
            {   // scatter A (with tf32 rounding)
                const int r = f >> 3, c4 = f & 7;
                const int mt = r >> 4, ir = r & 15;
                float vals[4] = {av[i].x, av[i].y, av[i].z, av[i].w};
#pragma unroll
                for (int e = 0; e < 4; e++) {
                    const int kl = c4 * 4 + e;
                    const int kk = kl >> 3, cc = kl & 7;
                    const int ln = (ir & 7) * 4 + (cc & 3);
                    const int sl = (ir >> 3) + ((cc >> 2) << 1);
                    As[(((kk << 3) + mt) * 32 + ln) * 4 + sl] = __uint_as_float(f2tf32(vals[e]));
                }
            }
            {   // scatter B
                const int kr = f >> 5, cb4 = f & 31;
                const int kk = kr >> 3, krr = kr & 7;
                float vals[4] = {bv4[i].x, bv4[i].y, bv4[i].z, bv4[i].w};
#pragma unroll
                for (int e = 0; e < 4; e++) {
                    const int nl = cb4 * 4 + e;
                    const int nt = nl >> 3, nc = nl & 7;
                    const int ln = nc * 4 + (krr & 3);
                    const int sl = krr >> 2;
                    Bs[(((kk << 4) + nt) * 32 + ln) * 2 + sl] = __uint_as_float(f2tf32(vals[e]));
                }
            }
        }
        __syncthreads();

#pragma unroll
        for (int kk = 0; kk < 4; kk++) {
            uint32_t af[4][4];
            uint32_t bf[4][2];
#pragma unroll
            for (int mt = 0; mt < 4; mt++) {
                float4 t = *(const float4*)&As[(((kk << 3) + (wm * 4 + mt)) * 32 + lane) * 4];
                af[mt][0] = __float_as_uint(t.x); af[mt][1] = __float_as_uint(t.y);
                af[mt][2] = __float_as_uint(t.z); af[mt][3] = __float_as_uint(t.w);
            }
#pragma unroll
            for (int nt = 0; nt < 4; nt++) {
                float2 t = *(const float2*)&Bs[(((kk << 4) + (wn * 4 + nt)) * 32 + lane) * 2];
                bf[nt][0] = __float_as_uint(t.x); bf[nt][1] = __float_as_uint(t.y);
            }
#pragma unroll
            for (int mt = 0; mt < 4; mt++)
#pragma unroll
                for (int nt = 0; nt < 4; nt++)
                    mma_tf32(c[mt][nt], af[mt][0], af[mt][1], af[mt][2], af[mt][3],
                             bf[nt][0], bf[nt][1]);
        }
    }

    // epilogue: bias, scale (q), scatter to [B,H,S,64]
    const int m_base = bm * 128 + wm * 64;
#pragma unroll
    for (int nt = 0; nt < 4; nt++) {
        const int ncl = wn * 32 + nt * 8 + tig * 2;       // col within block tile
        const float bias0 = bias[ncol0 + ncl];
        const float bias1 = bias[ncol0 + ncl + 1];
        const int nn = (n0 - sub) + ncl;                  // col within dst matrix
        const int h = nn >> 6, dd = nn & 63;
#pragma unroll
        for (int mt = 0; mt < 4; mt++) {
            const int r0 = m_base + mt * 16 + gid;
#pragma unroll
            for (int half = 0; half < 2; half++) {
                const int row = r0 + half * 8;
                const int b_ = row >> 11, s = row & (SS - 1);
                float2 st;
                st.x = (c[mt][nt][half * 2 + 0] + bias0) * scale;
                st.y = (c[mt][nt][half * 2 + 1] + bias1) * scale;
                *(float2*)&dst[(((size_t)(b_ * HH + h)) * SS + s) * DH + dd] = st;
            }
        }
    }
}

// ---------------------------------------------------------------------------
// Kernel 2: causal flash attention, tf32 mma (FA2 style).
// Block = 64 q rows of one (b,h); 4 warps x 16 rows. KV tiles of 64 keys.
// ---------------------------------------------------------------------------
__global__ __launch_bounds__(128) void attn_tf32(float* __restrict__ out)
{
    extern __shared__ float sm[];
    float* Qs = sm;            // [w(4)][kk(8)][lane(32)][4]  16 KB (A frags)
    float* Ks = sm + 4096;     // [kk(8)][nt(8)][lane(32)][2] 16 KB (B frags, n=keys,k=dh)
    float* Vs = sm + 8192;     // [kk2(8)][nt2(8)][lane(32)][2] 16 KB (B frags, k=keys,n=dh)
    float* Ps = sm + 12288;    // [w(4)][kk2(8)][lane(32)][4] 16 KB (A frags, per-warp)

    const int qt = blockIdx.x, h = blockIdx.y, b = blockIdx.z;
    const int tid = threadIdx.x, warp = tid >> 5, lane = tid & 31;
    const int gid = lane >> 2, tig = lane & 3;

    const size_t head = ((size_t)(b * HH + h)) * SS * DH;
    const float* qb = g_q + head;
    const float* kb = g_k + head;
    const float* vb = g_v + head;
    const int q0 = qt * 64;

    // Load Q tile (64 x 64) into fragment-permuted smem (with tf32 rounding)
#pragma unroll
    for (int i = 0; i < 8; i++) {
        const int f = tid + i * 128;
        const int r = f >> 4, c4 = f & 15;
        float4 t = *(const float4*)&qb[(size_t)(q0 + r) * DH + c4 * 4];
        const int w = r >> 4, ir = r & 15;
        float vals[4] = {t.x, t.y, t.z, t.w};
#pragma unroll
        for (int e = 0; e < 4; e++) {
            const int cl = c4 * 4 + e;
            const int kk = cl >> 3, cc = cl & 7;
            const int ln = (ir & 7) * 4 + (cc & 3);
            const int sl = (ir >> 3) + ((cc >> 2) << 1);
            Qs[(((w << 3) + kk) * 32 + ln) * 4 + sl] = __uint_as_float(f2tf32(vals[e]));
        }
    }
    __syncthreads();

    // Cache this warp's Q fragments in registers (reused for every KV tile)
    uint32_t qa[8][4];
#pragma unroll
    for (int kk = 0; kk < 8; kk++) {
        float4 t = *(const float4*)&Qs[(((warp << 3) + kk) * 32 + lane) * 4];
        qa[kk][0] = __float_as_uint(t.x); qa[kk][1] = __float_as_uint(t.y);
        qa[kk][2] = __float_as_uint(t.z); qa[kk][3] = __float_as_uint(t.w);
    }

    float O[8][4];
#pragma unroll
    for (int n = 0; n < 8; n++)
#pragma unroll
        for (int s = 0; s < 4; s++) O[n][s] = 0.f;
    float m_a = -1e30f, m_b = -1e30f, l_a = 0.f, l_b = 0.f;

    for (int kt = 0; kt <= qt; kt++) {
        const int k0 = kt * 64;
        __syncthreads();   // previous iteration done reading Ks/Vs (and Ps WAR)
        // Load K and V tiles (64 keys x 64 dh each) into fragment-permuted smem
#pragma unroll
        for (int i = 0; i < 8; i++) {
            const int f = tid + i * 128;
            const int j = f >> 4, c4 = f & 15;
            float4 kv = *(const float4*)&kb[(size_t)(k0 + j) * DH + c4 * 4];
            float4 vv = *(const float4*)&vb[(size_t)(k0 + j) * DH + c4 * 4];
            float kvals[4] = {kv.x, kv.y, kv.z, kv.w};
            float vvals[4] = {vv.x, vv.y, vv.z, vv.w};
#pragma unroll
            for (int e = 0; e < 4; e++) {
                const int cl = c4 * 4 + e;
                // K: n = key j, k-dim = dh
                {
                    const int nt = j >> 3, nc = j & 7;
                    const int kk = cl >> 3, kr = cl & 7;
                    const int ln = nc * 4 + (kr & 3);
                    const int sl = kr >> 2;
                    Ks[(((kk << 3) + nt) * 32 + ln) * 2 + sl] = __uint_as_float(f2tf32(kvals[e]));
                }
                // V: k-dim = key j, n = dh
                {
                    const int kk2 = j >> 3, kr = j & 7;
                    const int nt2 = cl >> 3, nc = cl & 7;
                    const int ln = nc * 4 + (kr & 3);
                    const int sl = kr >> 2;
                    Vs[(((kk2 << 3) + nt2) * 32 + ln) * 2 + sl] = __uint_as_float(f2tf32(vvals[e]));
                }
            }
        }
        __syncthreads();

        // S = Q @ K^T   (q pre-scaled by 1/8 in projection)
        float S[8][4];
#pragma unroll
        for (int n = 0; n < 8; n++)
#pragma unroll
            for (int s = 0; s < 4; s++) S[n][s] = 0.f;
#pragma unroll
        for (int kk = 0; kk < 8; kk++) {
#pragma unroll
            for (int nt = 0; nt < 8; nt++) {
                float2 t = *(const float2*)&Ks[(((kk << 3) + nt) * 32 + lane) * 2];
                mma_tf32(S[nt], qa[kk][0], qa[kk][1], qa[kk][2], qa[kk][3],
                         __float_as_uint(t.x), __float_as_uint(t.y));
            }
        }

        // Causal mask (diagonal tile only; k0 == q0 there)
        if (kt == qt) {
#pragma unroll
            for (int nt = 0; nt < 8; nt++)
#pragma unroll
                for (int sl = 0; sl < 4; sl++) {
                    const int key = nt * 8 + tig * 2 + (sl & 1);
                    const int row = warp * 16 + gid + (sl >> 1) * 8;
                    if (key > row) S[nt][sl] = -1e30f;
                }
        }

        // Online softmax (rows a: slots 0,1; rows b: slots 2,3)
        float mx_a = -1e30f, mx_b = -1e30f;
#pragma unroll
        for (int nt = 0; nt < 8; nt++) {
            mx_a = fmaxf(mx_a, fmaxf(S[nt][0], S[nt][1]));
            mx_b = fmaxf(mx_b, fmaxf(S[nt][2], S[nt][3]));
        }
        mx_a = fmaxf(mx_a, __shfl_xor_sync(0xffffffffu, mx_a, 1));
        mx_a = fmaxf(mx_a, __shfl_xor_sync(0xffffffffu, mx_a, 2));
        mx_b = fmaxf(mx_b, __shfl_xor_sync(0xffffffffu, mx_b, 1));
        mx_b = fmaxf(mx_b, __shfl_xor_sync(0xffffffffu, mx_b, 2));

        const float na = fmaxf(m_a, mx_a), nb = fmaxf(m_b, mx_b);
        const float ca = __expf(m_a - na), cb = __expf(m_b - nb);
        m_a = na; m_b = nb;

        float sa = 0.f, sb = 0.f;
#pragma unroll
        for (int nt = 0; nt < 8; nt++) {
#pragma unroll
            for (int sl = 0; sl < 4; sl++) {
                const float p = __expf(S[nt][sl] - ((sl < 2) ? na : nb));
                const uint32_t pt = f2tf32(p);              // round BEFORE summing:
                const float ptf = __uint_as_float(pt);      // numerator==denominator
                if (sl < 2) sa += ptf; else sb += ptf;
                // store into per-warp A-fragment layout for the PV mma
                const int ln = gid * 4 + (tig & 1) * 2 + (sl & 1);
                const int sp = (sl >> 1) + (tig >> 1) * 2;
                Ps[(((warp << 3) + nt) * 32 + ln) * 4 + sp] = ptf;
            }
        }
        sa += __shfl_xor_sync(0xffffffffu, sa, 1);
        sa += __shfl_xor_sync(0xffffffffu, sa, 2);
        sb += __shfl_xor_sync(0xffffffffu, sb, 1);
        sb += __shfl_xor_sync(0xffffffffu, sb, 2);
        l_a = l_a * ca + sa;
        l_b = l_b * cb + sb;
#pragma unroll
        for (int n = 0; n < 8; n++) {
            O[n][0] *= ca; O[n][1] *= ca; O[n][2] *= cb; O[n][3] *= cb;
        }

        __syncwarp();   // Ps is per-warp: warp-level fence is enough

        // O += P @ V
#pragma unroll
        for (int kk2 = 0; kk2 < 8; kk2++) {
            float4 pf = *(const float4*)&Ps[(((warp << 3) + kk2) * 32 + lane) * 4];
            const uint32_t p0 = __float_as_uint(pf.x), p1 = __float_as_uint(pf.y);
            const uint32_t p2 = __float_as_uint(pf.z), p3 = __float_as_uint(pf.w);
#pragma unroll
            for (int nt2 = 0; nt2 < 8; nt2++) {
                float2 t = *(const float2*)&Vs[(((kk2 << 3) + nt2) * 32 + lane) * 2];
                mma_tf32(O[nt2], p0, p1, p2, p3,
                         __float_as_uint(t.x), __float_as_uint(t.y));
            }
        }
    }

    // Epilogue: normalize and write out[b, q, h*64 + d]
    const float inva = 1.f / l_a, invb = 1.f / l_b;
    const int ra = q0 + warp * 16 + gid;
    const int rb = ra + 8;
    float* oa = out + ((size_t)(b * SS + ra)) * (HH * DH) + (size_t)h * DH;
    float* ob = out + ((size_t)(b * SS + rb)) * (HH * DH) + (size_t)h * DH;
#pragma unroll
    for (int nt2 = 0; nt2 < 8; nt2++) {
        const int col = nt2 * 8 + tig * 2;
        float2 sa2, sb2;
        sa2.x = O[nt2][0] * inva; sa2.y = O[nt2][1] * inva;
        sb2.x = O[nt2][2] * invb; sb2.y = O[nt2][3] * invb;
        *(float2*)&oa[col] = sa2;
        *(float2*)&ob[col] = sb2;
    }
}

// ---------------------------------------------------------------------------
extern "C" void kernel_launch(void* const* d_in, const int* in_sizes, int n_in,
                              void* d_out, int out_size)
{
    const float* x   = (const float*)d_in[0];
    const float* Wqk = (const float*)d_in[1];
    const float* bqk = (const float*)d_in[2];
    const float* Wv  = (const float*)d_in[3];
    const float* bv  = (const float*)d_in[4];
    float* out = (float*)d_out;

    // GEMM: grid (3072/128, 4096/128) = (24, 32)
    dim3 g1(NTOT / 128, (BB * SS) / 128);
    qkv_gemm_tf32<<<g1, 256>>>(x, Wqk, bqk, Wv, bv);

    // Attention: 64 KB dynamic smem
    const int smem_bytes = 16384 * sizeof(float);
    static int attr_set = 0;
    if (!attr_set) {
        cudaFuncSetAttribute(attn_tf32, cudaFuncAttributeMaxDynamicSharedMemorySize,
                             smem_bytes);
        attr_set = 1;
    }
    dim3 g2(SS / 64, HH, BB);
    attn_tf32<<<g2, 128, smem_bytes>>>(out);
}

// round 8
// speedup vs baseline: 5.5335x; 3.2733x over previous
#include <cuda_runtime.h>
#include <cstdint>

#define BB 2
#define SS 2048
#define DD 1024
#define HH 16
#define NQK 2048
#define NTOT 3072

// tf32 fragment-permuted scratch (all values pre-rounded to tf32):
// g_x4 : x as A-frags   [mtg(256)][kkg(128)][lane(32)][slot(4)]
// g_w  : W as B-frags   [ntg(384)][kkg(128)][lane(32)][slot(2)]
// g_qp : q as A-frags   [head(32)][rg(128)][kk(8)][lane(32)][slot(4)]   (q pre-scaled 1/8)
// g_kp : k as B-frags   [head(32)][sg(256)][kk(8)][lane(32)][slot(2)]   (n=key, k=dh)
// g_vp : v as B-frags   [head(32)][sg(256)][nt2(8)][lane(32)][slot(2)]  (k=key, n=dh)
__device__ float g_x4[4194304];
__device__ float g_w [3145728];
__device__ float g_qp[4194304];
__device__ float g_kp[4194304];
__device__ float g_vp[4194304];

// ---------------------------------------------------------------------------
__device__ __forceinline__ uint32_t f2tf32(float x) {
    uint32_t r; asm("cvt.rna.tf32.f32 %0, %1;" : "=r"(r) : "f"(x)); return r;
}
__device__ __forceinline__ float f2tf32f(float x) { return __uint_as_float(f2tf32(x)); }

__device__ __forceinline__ void mma_tf32(float c[4],
                                         uint32_t a0, uint32_t a1, uint32_t a2, uint32_t a3,
                                         uint32_t b0, uint32_t b1) {
    asm volatile(
        "mma.sync.aligned.m16n8k8.row.col.f32.tf32.tf32.f32 "
        "{%0,%1,%2,%3}, {%4,%5,%6,%7}, {%8,%9}, {%0,%1,%2,%3};"
        : "+f"(c[0]), "+f"(c[1]), "+f"(c[2]), "+f"(c[3])
        : "r"(a0), "r"(a1), "r"(a2), "r"(a3), "r"(b0), "r"(b1));
}

__device__ __forceinline__ void cp16(uint32_t dst, const void* src) {
    asm volatile("cp.async.cg.shared.global [%0], [%1], 16;" :: "r"(dst), "l"(src));
}
#define CP_COMMIT() asm volatile("cp.async.commit_group;" ::: "memory")
#define CP_WAIT0()  asm volatile("cp.async.wait_group 0;" ::: "memory")

// ---------------------------------------------------------------------------
// Prepass: x -> A-frag tf32 layout. One thread = one (chunk, lane) float4.
// ---------------------------------------------------------------------------
__global__ __launch_bounds__(256) void prep_x(const float* __restrict__ x)
{
    const int g = blockIdx.x * 256 + threadIdx.x;   // 0..1048575
    const int lane = g & 31, c = g >> 5;            // chunk 0..32767
    const int kkg = c & 127, mtg = c >> 7;
    float4 o;
    float* po = (float*)&o;
#pragma unroll
    for (int sl = 0; sl < 4; sl++) {
        const int ir = (lane >> 2) + (sl & 1) * 8;
        const int cc = (lane & 3) + (sl >> 1) * 4;
        po[sl] = f2tf32f(x[(size_t)(mtg * 16 + ir) * DD + kkg * 8 + cc]);
    }
    *(float4*)&g_x4[(size_t)c * 128 + lane * 4] = o;
}

// Prepass: [Wqk|Wv] -> B-frag tf32 layout. One thread = one (chunk, lane) float2.
__global__ __launch_bounds__(256) void prep_w(const float* __restrict__ Wqk,
                                              const float* __restrict__ Wv)
{
    const int g = blockIdx.x * 256 + threadIdx.x;   // 0..1572863
    const int lane = g & 31, c = g >> 5;            // chunk 0..49151
    const int kkg = c & 127, ntg = c >> 7;          // ntg 0..383
    const int n = ntg * 8 + (lane >> 2);
    const float* W; int ldw, col;
    if (n < NQK) { W = Wqk; ldw = NQK; col = n; }
    else         { W = Wv;  ldw = DD;  col = n - NQK; }
    float2 o;
#pragma unroll
    for (int sl = 0; sl < 2; sl++) {
        const int kr = (lane & 3) + sl * 4;
        ((float*)&o)[sl] = f2tf32f(W[(size_t)(kkg * 8 + kr) * ldw + col]);
    }
    *(float2*)&g_w[(size_t)c * 64 + lane * 2] = o;
}

// ---------------------------------------------------------------------------
// QKV GEMM: 128x128 block tile, k-step 32, cp.async double-buffered.
// Epilogue scatters tf32 q/k/v into fragment-permuted gmem layouts.
// ---------------------------------------------------------------------------
__global__ __launch_bounds__(256, 2) void qkv_gemm(const float* __restrict__ bqk,
                                                   const float* __restrict__ bv)
{
    extern __shared__ float sm[];
    const uint32_t sb = (uint32_t)__cvta_generic_to_shared(sm);
    // As(buf) = sm + buf*4096 floats; Bs(buf) = sm + 8192 + buf*4096 floats.

    const int bm = blockIdx.y, bn = blockIdx.x;
    const int n0 = bn * 128;
    const int tid = threadIdx.x, warp = tid >> 5, lane = tid & 31;
    const int wm = warp >> 2, wn = warp & 3;
    const int gid = lane >> 2, tig = lane & 3;

    float c[4][4][4];
#pragma unroll
    for (int i = 0; i < 4; i++)
#pragma unroll
        for (int j = 0; j < 4; j++)
#pragma unroll
            for (int s = 0; s < 4; s++) c[i][j][s] = 0.f;

    auto load_tile = [&](int it, int buf) {
        const int kkg0 = it * 4;
#pragma unroll
        for (int i = 0; i < 4; i++) {       // A: 32 chunks x 512B
            const int id = tid + i * 256;
            const int chunk = id >> 5, off = id & 31;
            const int kk = chunk >> 3, mt = chunk & 7;
            const float* src = &g_x4[((size_t)(bm * 8 + mt) * 128 + kkg0 + kk) * 128 + off * 4];
            cp16(sb + (buf * 4096 + chunk * 128 + off * 4) * 4, src);
        }
#pragma unroll
        for (int i = 0; i < 4; i++) {       // B: 64 chunks x 256B
            const int id = tid + i * 256;
            const int chunk = id >> 4, off = id & 15;
            const int kk = chunk >> 4, nt = chunk & 15;
            const float* src = &g_w[((size_t)(bn * 16 + nt) * 128 + kkg0 + kk) * 64 + off * 4];
            cp16(sb + (8192 + buf * 4096 + chunk * 64 + off * 4) * 4, src);
        }
    };

    load_tile(0, 0);
    CP_COMMIT();

    for (int it = 0; it < 32; it++) {
        const int buf = it & 1;
        CP_WAIT0();
        __syncthreads();
        if (it + 1 < 32) { load_tile(it + 1, 1 - buf); CP_COMMIT(); }

        const float* As = sm + buf * 4096;
        const float* Bs = sm + 8192 + buf * 4096;
#pragma unroll
        for (int kk = 0; kk < 4; kk++) {
            uint32_t af[4][4], bf[4][2];
#pragma unroll
            for (int mt = 0; mt < 4; mt++) {
                float4 t = *(const float4*)&As[(((kk << 3) + (wm * 4 + mt)) * 32 + lane) * 4];
                af[mt][0] = __float_as_uint(t.x); af[mt][1] = __float_as_uint(t.y);
                af[mt][2] = __float_as_uint(t.z); af[mt][3] = __float_as_uint(t.w);
            }
#pragma unroll
            for (int nt = 0; nt < 4; nt++) {
                float2 t = *(const float2*)&Bs[(((kk << 4) + (wn * 4 + nt)) * 32 + lane) * 2];
                bf[nt][0] = __float_as_uint(t.x); bf[nt][1] = __float_as_uint(t.y);
            }
#pragma unroll
            for (int mt = 0; mt < 4; mt++)
#pragma unroll
                for (int nt = 0; nt < 4; nt++)
                    mma_tf32(c[mt][nt], af[mt][0], af[mt][1], af[mt][2], af[mt][3],
                             bf[nt][0], bf[nt][1]);
        }
    }

    // Epilogue: bias, q-scale, tf32-round, scatter to fragment-permuted q/k/v
    const int typ = (n0 < DD) ? 0 : (n0 < NQK ? 1 : 2);
    const float* bias = (typ == 2) ? bv : bqk;
    const int bcol0 = (typ == 2) ? (n0 - NQK) : n0;
    const int nnbase = (typ == 0) ? n0 : (typ == 1 ? n0 - DD : n0 - NQK);

#pragma unroll
    for (int nt = 0; nt < 4; nt++) {
        const int ncl = wn * 32 + nt * 8 + tig * 2;
        const float b0 = bias[bcol0 + ncl];
        const float b1 = bias[bcol0 + ncl + 1];
        const int nn = nnbase + ncl;
        const int h = nn >> 6;
        const int d0 = nn & 63;
#pragma unroll
        for (int mt = 0; mt < 4; mt++) {
#pragma unroll
            for (int half = 0; half < 2; half++) {
                const int m = bm * 128 + wm * 64 + mt * 16 + gid + half * 8;
                const int bb = m >> 11, s = m & (SS - 1);
                const int head = bb * HH + h;
                float v0 = c[mt][nt][half * 2 + 0] + b0;
                float v1 = c[mt][nt][half * 2 + 1] + b1;
                if (typ == 0) {
                    v0 *= 0.125f; v1 *= 0.125f;
                    const int rg = s >> 4, ir = s & 15;
                    const int kk = d0 >> 3;
                    const int cc0 = d0 & 7, cc1 = cc0 + 1;
                    const int lnb = (ir & 7) * 4;
                    const int slb = ir >> 3;
                    const size_t base = (((size_t)head * 128 + rg) * 8 + kk) * 128;
                    g_qp[base + (lnb + (cc0 & 3)) * 4 + slb + ((cc0 >> 2) << 1)] = f2tf32f(v0);
                    g_qp[base + (lnb + (cc1 & 3)) * 4 + slb + ((cc1 >> 2) << 1)] = f2tf32f(v1);
                } else if (typ == 1) {
                    const int sg = s >> 3, nc = s & 7;
                    const int kk = d0 >> 3;
                    const int kr0 = d0 & 7, kr1 = kr0 + 1;
                    const size_t base = (((size_t)head * 256 + sg) * 8 + kk) * 64;
                    g_kp[base + (nc * 4 + (kr0 & 3)) * 2 + (kr0 >> 2)] = f2tf32f(v0);
                    g_kp[base + (nc * 4 + (kr1 & 3)) * 2 + (kr1 >> 2)] = f2tf32f(v1);
                } else {
                    const int sg = s >> 3, kr = s & 7;
                    const int nt2 = d0 >> 3;
                    const int nc0 = d0 & 7, nc1 = nc0 + 1;
                    const size_t base = (((size_t)head * 256 + sg) * 8 + nt2) * 64;
                    g_vp[base + (nc0 * 4 + (kr & 3)) * 2 + (kr >> 2)] = f2tf32f(v0);
                    g_vp[base + (nc1 * 4 + (kr & 3)) * 2 + (kr >> 2)] = f2tf32f(v1);
                }
            }
        }
    }
}

// ---------------------------------------------------------------------------
// Causal flash attention: 128 q rows/block (8 warps x 16 rows), 64-key KV
// tiles double-buffered via cp.async (bulk contiguous copies, pre-permuted
// tf32 data). P transposed C-frag -> A-frag via shfl (no smem round trip).
// ---------------------------------------------------------------------------
__global__ __launch_bounds__(256, 2) void attn_kernel(float* __restrict__ out)
{
    extern __shared__ float sm[];
    const uint32_t sb = (uint32_t)__cvta_generic_to_shared(sm);
    // buffer buf: K at sm + buf*8192 (4096 floats), V at +4096.

    const int qt = (gridDim.x - 1) - blockIdx.x;   // heavy blocks first
    const int head = blockIdx.y;
    const int b = head >> 4, h = head & 15;
    const int tid = threadIdx.x, warp = tid >> 5, lane = tid & 31;
    const int gid = lane >> 2, tig = lane & 3;
    const int q0 = qt * 128;

    // Q fragments for this warp's 16 rows (one coalesced 512B load per kk)
    const float* qsrc = g_qp + ((size_t)head * 128 + qt * 8 + warp) * 1024;
    uint32_t qa[8][4];
#pragma unroll
    for (int kk = 0; kk < 8; kk++) {
        float4 t = *(const float4*)&qsrc[kk * 128 + lane * 4];
        qa[kk][0] = __float_as_uint(t.x); qa[kk][1] = __float_as_uint(t.y);
        qa[kk][2] = __float_as_uint(t.z); qa[kk][3] = __float_as_uint(t.w);
    }

    float O[8][4];
#pragma unroll
    for (int n = 0; n < 8; n++)
#pragma unroll
        for (int s = 0; s < 4; s++) O[n][s] = 0.f;
    float m_a = -1e30f, m_b = -1e30f, l_a = 0.f, l_b = 0.f;

    const int KTILES = 2 * qt + 2;
    const float* kbase = g_kp + (size_t)head * 131072;   // 256 groups * 512
    const float* vbase = g_vp + (size_t)head * 131072;

    // prologue: tile 0 -> buf 0 (two contiguous 16KB copies)
#pragma unroll
    for (int i = 0; i < 4; i++) {
        const int id = tid + i * 256;
        cp16(sb + id * 16, kbase + id * 4);
        cp16(sb + 16384 + id * 16, vbase + id * 4);
    }
    CP_COMMIT();

    for (int kt = 0; kt < KTILES; kt++) {
        const int buf = kt & 1;
        CP_WAIT0();
        __syncthreads();
        if (kt + 1 < KTILES) {
            const float* ks = kbase + (size_t)(kt + 1) * 4096;
            const float* vs = vbase + (size_t)(kt + 1) * 4096;
            const uint32_t db = sb + (1 - buf) * 32768;
#pragma unroll
            for (int i = 0; i < 4; i++) {
                const int id = tid + i * 256;
                cp16(db + id * 16, ks + id * 4);
                cp16(db + 16384 + id * 16, vs + id * 4);
            }
            CP_COMMIT();
        }

        const float* Ks = sm + buf * 8192;
        const float* Vs = sm + buf * 8192 + 4096;
        const int k0 = kt * 64;

        // S = Q @ K^T
        float S[8][4];
#pragma unroll
        for (int n = 0; n < 8; n++)
#pragma unroll
            for (int s = 0; s < 4; s++) S[n][s] = 0.f;
#pragma unroll
        for (int kk = 0; kk < 8; kk++) {
#pragma unroll
            for (int nt = 0; nt < 8; nt++) {
                float2 t = *(const float2*)&Ks[nt * 512 + kk * 64 + lane * 2];
                mma_tf32(S[nt], qa[kk][0], qa[kk][1], qa[kk][2], qa[kk][3],
                         __float_as_uint(t.x), __float_as_uint(t.y));
            }
        }

        // causal mask (skip for fully-past tiles)
        if (k0 + 63 > q0 + warp * 16) {
#pragma unroll
            for (int nt = 0; nt < 8; nt++)
#pragma unroll
                for (int sl = 0; sl < 4; sl++) {
                    const int key = k0 + nt * 8 + tig * 2 + (sl & 1);
                    const int row = q0 + warp * 16 + gid + (sl >> 1) * 8;
                    if (key > row) S[nt][sl] = -1e30f;
                }
        }

        // online softmax (rows a: slots 0,1; rows b: slots 2,3)
        float mx_a = -1e30f, mx_b = -1e30f;
#pragma unroll
        for (int nt = 0; nt < 8; nt++) {
            mx_a = fmaxf(mx_a, fmaxf(S[nt][0], S[nt][1]));
            mx_b = fmaxf(mx_b, fmaxf(S[nt][2], S[nt][3]));
        }
        mx_a = fmaxf(mx_a, __shfl_xor_sync(0xffffffffu, mx_a, 1));
        mx_a = fmaxf(mx_a, __shfl_xor_sync(0xffffffffu, mx_a, 2));
        mx_b = fmaxf(mx_b, __shfl_xor_sync(0xffffffffu, mx_b, 1));
        mx_b = fmaxf(mx_b, __shfl_xor_sync(0xffffffffu, mx_b, 2));

        const float na = fmaxf(m_a, mx_a), nb = fmaxf(m_b, mx_b);
        const float ca = __expf(m_a - na), cb = __expf(m_b - nb);
        m_a = na; m_b = nb;

        float sa = 0.f, sbv = 0.f;
#pragma unroll
        for (int nt = 0; nt < 8; nt++) {
#pragma unroll
            for (int sl = 0; sl < 4; sl++) {
                const float p = __expf(S[nt][sl] - ((sl < 2) ? na : nb));
                const float ptf = f2tf32f(p);      // round before summing
                if (sl < 2) sa += ptf; else sbv += ptf;
                S[nt][sl] = ptf;                   // S now holds P (tf32)
            }
        }
        sa  += __shfl_xor_sync(0xffffffffu, sa, 1);
        sa  += __shfl_xor_sync(0xffffffffu, sa, 2);
        sbv += __shfl_xor_sync(0xffffffffu, sbv, 1);
        sbv += __shfl_xor_sync(0xffffffffu, sbv, 2);
        l_a = l_a * ca + sa;
        l_b = l_b * cb + sbv;
#pragma unroll
        for (int n = 0; n < 8; n++) {
            O[n][0] *= ca; O[n][1] *= ca; O[n][2] *= cb; O[n][3] *= cb;
        }

        // O += P @ V : shfl-transpose P (C-frag) into A-frags per key group
        const int l0 = gid * 4 + (tig >> 1);
        const int l2 = l0 + 2;
        const bool odd = (tig & 1);
#pragma unroll
        for (int kk2 = 0; kk2 < 8; kk2++) {
            const float e00 = __shfl_sync(0xffffffffu, S[kk2][0], l0);
            const float e01 = __shfl_sync(0xffffffffu, S[kk2][1], l0);
            const float e10 = __shfl_sync(0xffffffffu, S[kk2][2], l0);
            const float e11 = __shfl_sync(0xffffffffu, S[kk2][3], l0);
            const float e20 = __shfl_sync(0xffffffffu, S[kk2][0], l2);
            const float e21 = __shfl_sync(0xffffffffu, S[kk2][1], l2);
            const float e30 = __shfl_sync(0xffffffffu, S[kk2][2], l2);
            const float e31 = __shfl_sync(0xffffffffu, S[kk2][3], l2);
            const uint32_t a0 = __float_as_uint(odd ? e01 : e00);
            const uint32_t a1 = __float_as_uint(odd ? e11 : e10);
            const uint32_t a2 = __float_as_uint(odd ? e21 : e20);
            const uint32_t a3 = __float_as_uint(odd ? e31 : e30);
#pragma unroll
            for (int nt2 = 0; nt2 < 8; nt2++) {
                float2 t = *(const float2*)&Vs[kk2 * 512 + nt2 * 64 + lane * 2];
                mma_tf32(O[nt2], a0, a1, a2, a3,
                         __float_as_uint(t.x), __float_as_uint(t.y));
            }
        }
    }

    // epilogue: normalize, write out[b, row, h*64 + col]
    const float inva = 1.f / l_a, invb = 1.f / l_b;
    const int ra = q0 + warp * 16 + gid;
    const int rb = ra + 8;
    float* oa = out + ((size_t)(b * SS + ra)) * DD + (size_t)h * 64;
    float* ob = out + ((size_t)(b * SS + rb)) * DD + (size_t)h * 64;
#pragma unroll
    for (int nt2 = 0; nt2 < 8; nt2++) {
        const int col = nt2 * 8 + tig * 2;
        float2 va, vb2;
        va.x  = O[nt2][0] * inva; va.y  = O[nt2][1] * inva;
        vb2.x = O[nt2][2] * invb; vb2.y = O[nt2][3] * invb;
        *(float2*)&oa[col] = va;
        *(float2*)&ob[col] = vb2;
    }
}

// ---------------------------------------------------------------------------
extern "C" void kernel_launch(void* const* d_in, const int* in_sizes, int n_in,
                              void* d_out, int out_size)
{
    const float* x   = (const float*)d_in[0];
    const float* Wqk = (const float*)d_in[1];
    const float* bqk = (const float*)d_in[2];
    const float* Wv  = (const float*)d_in[3];
    const float* bv  = (const float*)d_in[4];
    float* out = (float*)d_out;

    prep_x<<<4096, 256>>>(x);
    prep_w<<<6144, 256>>>(Wqk, Wv);

    cudaFuncSetAttribute(qkv_gemm, cudaFuncAttributeMaxDynamicSharedMemorySize, 65536);
    qkv_gemm<<<dim3(24, 32), 256, 65536>>>(bqk, bv);

    cudaFuncSetAttribute(attn_kernel, cudaFuncAttributeMaxDynamicSharedMemorySize, 65536);
    attn_kernel<<<dim3(16, 32), 256, 65536>>>(out);
}

// round 9
// speedup vs baseline: 6.5934x; 1.1915x over previous
#include <cuda_runtime.h>
#include <cstdint>

#define BB 2
#define SS 2048
#define DD 1024
#define HH 16
#define NQK 2048
#define NTOT 3072

// tf32 fragment-permuted scratch (all values pre-rounded to tf32):
// g_x4 : x as A-frags        [mtg(256)][kkg(128)][lane(32)][slot(4)]
// g_w  : W as PAIRED B-frags [ntpg(192)][kkg(128)][lane(32)][4]
// g_qp : q as A-frags        [head(32)][rg(128)][kk(8)][lane(32)][slot(4)] (q pre-scaled 1/8)
// g_kp : k as PAIRED B-frags [head(32)][tile(32)][kk(8)][ntp(4)][lane(32)][4] (n=key,k=dh)
// g_vp : v as PAIRED B-frags [head(32)][tile(32)][kk2(8)][ntp2(4)][lane(32)][4] (k=key,n=dh)
__device__ float g_x4[4194304];
__device__ float g_w [3145728];
__device__ float g_qp[4194304];
__device__ float g_kp[4194304];
__device__ float g_vp[4194304];

// ---------------------------------------------------------------------------
__device__ __forceinline__ uint32_t f2tf32(float x) {
    uint32_t r; asm("cvt.rna.tf32.f32 %0, %1;" : "=r"(r) : "f"(x)); return r;
}
__device__ __forceinline__ float f2tf32f(float x) { return __uint_as_float(f2tf32(x)); }

__device__ __forceinline__ void mma_tf32(float c[4],
                                         uint32_t a0, uint32_t a1, uint32_t a2, uint32_t a3,
                                         uint32_t b0, uint32_t b1) {
    asm volatile(
        "mma.sync.aligned.m16n8k8.row.col.f32.tf32.tf32.f32 "
        "{%0,%1,%2,%3}, {%4,%5,%6,%7}, {%8,%9}, {%0,%1,%2,%3};"
        : "+f"(c[0]), "+f"(c[1]), "+f"(c[2]), "+f"(c[3])
        : "r"(a0), "r"(a1), "r"(a2), "r"(a3), "r"(b0), "r"(b1));
}

__device__ __forceinline__ void cp16(uint32_t dst, const void* src) {
    asm volatile("cp.async.cg.shared.global [%0], [%1], 16;" :: "r"(dst), "l"(src));
}
#define CP_COMMIT() asm volatile("cp.async.commit_group;" ::: "memory")
#define CP_WAIT0()  asm volatile("cp.async.wait_group 0;" ::: "memory")

// ---------------------------------------------------------------------------
// Prepass: x -> A-frag tf32 layout.
// ---------------------------------------------------------------------------
__global__ __launch_bounds__(256) void prep_x(const float* __restrict__ x)
{
    const int g = blockIdx.x * 256 + threadIdx.x;
    const int lane = g & 31, c = g >> 5;            // chunk 0..32767
    const int kkg = c & 127, mtg = c >> 7;
    float4 o;
    float* po = (float*)&o;
#pragma unroll
    for (int sl = 0; sl < 4; sl++) {
        const int ir = (lane >> 2) + (sl & 1) * 8;
        const int cc = (lane & 3) + (sl >> 1) * 4;
        po[sl] = f2tf32f(x[(size_t)(mtg * 16 + ir) * DD + kkg * 8 + cc]);
    }
    *(float4*)&g_x4[(size_t)c * 128 + lane * 4] = o;
}

// Prepass: [Wqk|Wv] -> pair-packed B-frag tf32 layout.
// float4 = (nt even: b0,b1, nt odd: b0,b1) for ntg pair (2*ntpg, 2*ntpg+1).
__global__ __launch_bounds__(256) void prep_w(const float* __restrict__ Wqk,
                                              const float* __restrict__ Wv)
{
    const int g = blockIdx.x * 256 + threadIdx.x;   // 0..786431
    const int lane = g & 31, c = g >> 5;            // chunk 0..24575
    const int kkg = c & 127, ntpg = c >> 7;         // ntpg 0..191
    float4 o;
    float* po = (float*)&o;
#pragma unroll
    for (int sub = 0; sub < 4; sub++) {
        const int pnt = sub >> 1, sl = sub & 1;
        const int n = (ntpg * 2 + pnt) * 8 + (lane >> 2);
        const int k = kkg * 8 + (lane & 3) + sl * 4;
        const float* W; int ldw, col;
        if (n < NQK) { W = Wqk; ldw = NQK; col = n; }
        else         { W = Wv;  ldw = DD;  col = n - NQK; }
        po[sub] = f2tf32f(W[(size_t)k * ldw + col]);
    }
    *(float4*)&g_w[(size_t)c * 128 + lane * 4] = o;
}

// ---------------------------------------------------------------------------
// QKV GEMM: 128x128 block tile, k-step 32, cp.async double-buffered.
// B frags pair-packed (LDS.128 -> 2 mma). Epilogue scatters tf32 q/k/v into
// fragment-permuted gmem layouts (k/v pair-packed).
// ---------------------------------------------------------------------------
__global__ __launch_bounds__(256, 2) void qkv_gemm(const float* __restrict__ bqk,
                                                   const float* __restrict__ bv)
{
    extern __shared__ float sm[];
    const uint32_t sb = (uint32_t)__cvta_generic_to_shared(sm);
    // As(buf) = sm + buf*4096; Bs(buf) = sm + 8192 + buf*4096 (floats).

    const int bm = blockIdx.y, bn = blockIdx.x;
    const int n0 = bn * 128;
    const int tid = threadIdx.x, warp = tid >> 5, lane = tid & 31;
    const int wm = warp >> 2, wn = warp & 3;
    const int gid = lane >> 2, tig = lane & 3;

    float c[4][4][4];
#pragma unroll
    for (int i = 0; i < 4; i++)
#pragma unroll
        for (int j = 0; j < 4; j++)
#pragma unroll
            for (int s = 0; s < 4; s++) c[i][j][s] = 0.f;

    auto load_tile = [&](int it, int buf) {
        const int kkg0 = it * 4;
#pragma unroll
        for (int i = 0; i < 4; i++) {       // A: 32 chunks x 512B
            const int id = tid + i * 256;
            const int chunk = id >> 5, off = id & 31;
            const int kk = chunk >> 3, mt = chunk & 7;
            const float* src = &g_x4[((size_t)(bm * 8 + mt) * 128 + kkg0 + kk) * 128 + off * 4];
            cp16(sb + (buf * 4096 + chunk * 128 + off * 4) * 4, src);
        }
#pragma unroll
        for (int i = 0; i < 4; i++) {       // B: 32 chunks x 512B (paired)
            const int id = tid + i * 256;
            const int chunk = id >> 5, off = id & 31;
            const int kk = chunk >> 3, ntp = chunk & 7;
            const float* src = &g_w[((size_t)(bn * 8 + ntp) * 128 + kkg0 + kk) * 128 + off * 4];
            cp16(sb + (8192 + buf * 4096 + chunk * 128 + off * 4) * 4, src);
        }
    };

    load_tile(0, 0);
    CP_COMMIT();

    for (int it = 0; it < 32; it++) {
        const int buf = it & 1;
        CP_WAIT0();
        __syncthreads();
        if (it + 1 < 32) { load_tile(it + 1, 1 - buf); CP_COMMIT(); }

        const float* As = sm + buf * 4096;
        const float* Bs = sm + 8192 + buf * 4096;
#pragma unroll
        for (int kk = 0; kk < 4; kk++) {
            uint32_t af[4][4], bf[4][2];
#pragma unroll
            for (int mt = 0; mt < 4; mt++) {
                float4 t = *(const float4*)&As[(((kk << 3) + (wm * 4 + mt)) * 32 + lane) * 4];
                af[mt][0] = __float_as_uint(t.x); af[mt][1] = __float_as_uint(t.y);
                af[mt][2] = __float_as_uint(t.z); af[mt][3] = __float_as_uint(t.w);
            }
#pragma unroll
            for (int ntpi = 0; ntpi < 2; ntpi++) {   // pair-packed: 2 LDS.128 -> 4 frags
                float4 t = *(const float4*)&Bs[(((kk << 3) + (wn * 2 + ntpi)) * 32 + lane) * 4];
                bf[2 * ntpi][0]     = __float_as_uint(t.x);
                bf[2 * ntpi][1]     = __float_as_uint(t.y);
                bf[2 * ntpi + 1][0] = __float_as_uint(t.z);
                bf[2 * ntpi + 1][1] = __float_as_uint(t.w);
            }
#pragma unroll
            for (int mt = 0; mt < 4; mt++)
#pragma unroll
                for (int nt = 0; nt < 4; nt++)
                    mma_tf32(c[mt][nt], af[mt][0], af[mt][1], af[mt][2], af[mt][3],
                             bf[nt][0], bf[nt][1]);
        }
    }

    // Epilogue: bias, q-scale, tf32-round, scatter to fragment-permuted q/k/v
    const int typ = (n0 < DD) ? 0 : (n0 < NQK ? 1 : 2);
    const float* bias = (typ == 2) ? bv : bqk;
    const int bcol0 = (typ == 2) ? (n0 - NQK) : n0;
    const int nnbase = (typ == 0) ? n0 : (typ == 1 ? n0 - DD : n0 - NQK);

#pragma unroll
    for (int nt = 0; nt < 4; nt++) {
        const int ncl = wn * 32 + nt * 8 + tig * 2;
        const float b0 = bias[bcol0 + ncl];
        const float b1 = bias[bcol0 + ncl + 1];
        const int nn = nnbase + ncl;
        const int h = nn >> 6;
        const int d0 = nn & 63;      // even
#pragma unroll
        for (int mt = 0; mt < 4; mt++) {
#pragma unroll
            for (int half = 0; half < 2; half++) {
                const int m = bm * 128 + wm * 64 + mt * 16 + gid + half * 8;
                const int bb = m >> 11, s = m & (SS - 1);
                const int head = bb * HH + h;
                float v0 = c[mt][nt][half * 2 + 0] + b0;
                float v1 = c[mt][nt][half * 2 + 1] + b1;
                if (typ == 0) {
                    v0 *= 0.125f; v1 *= 0.125f;
                    const int rg = s >> 4, ir = s & 15;
                    const int kk = d0 >> 3;
                    const int cc0 = d0 & 7, cc1 = cc0 + 1;
                    const int lnb = (ir & 7) * 4;
                    const int slb = ir >> 3;
                    const size_t base = (((size_t)head * 128 + rg) * 8 + kk) * 128;
                    g_qp[base + (lnb + (cc0 & 3)) * 4 + slb + ((cc0 >> 2) << 1)] = f2tf32f(v0);
                    g_qp[base + (lnb + (cc1 & 3)) * 4 + slb + ((cc1 >> 2) << 1)] = f2tf32f(v1);
                } else if (typ == 1) {
                    // K pair-packed: [head][tile][kk][ntp][lane][4]
                    const int tile = s >> 6, j = s & 63;
                    const int ntp = j >> 4, pnt = (j >> 3) & 1, nc = j & 7;
                    const int kk = d0 >> 3;
                    const int kr0 = d0 & 7, kr1 = kr0 + 1;   // kr0 even
                    const size_t base = ((((size_t)head * 32 + tile) * 8 + kk) * 4 + ntp) * 128;
                    g_kp[base + (nc * 4 + (kr0 & 3)) * 4 + pnt * 2 + (kr0 >> 2)] = f2tf32f(v0);
                    g_kp[base + (nc * 4 + (kr1 & 3)) * 4 + pnt * 2 + (kr1 >> 2)] = f2tf32f(v1);
                } else {
                    // V pair-packed: [head][tile][kk2][ntp2][lane][4]
                    const int tile = s >> 6, j = s & 63;
                    const int kk2 = j >> 3, kr = j & 7;
                    const int ntp2 = d0 >> 4, pnt2 = (d0 >> 3) & 1;
                    const int nc0 = d0 & 7, nc1 = nc0 + 1;   // nc0 even, same nt2
                    const int sub = pnt2 * 2 + (kr >> 2);
                    const size_t base = ((((size_t)head * 32 + tile) * 8 + kk2) * 4 + ntp2) * 128;
                    g_vp[base + (nc0 * 4 + (kr & 3)) * 4 + sub] = f2tf32f(v0);
                    g_vp[base + (nc1 * 4 + (kr & 3)) * 4 + sub] = f2tf32f(v1);
                }
            }
        }
    }
}

// ---------------------------------------------------------------------------
// Causal flash attention: 128 q rows/block (8 warps x 16 rows), 64-key KV
// tiles double-buffered via bulk cp.async. K/V frags pair-packed:
// one LDS.128 feeds two mmas. P transposed C->A frag via shfl.
// Grid: (head, qt) with qt descending -> all heavy blocks launch first.
// ---------------------------------------------------------------------------
__global__ __launch_bounds__(256, 2) void attn_kernel(float* __restrict__ out)
{
    extern __shared__ float sm[];
    const uint32_t sb = (uint32_t)__cvta_generic_to_shared(sm);
    // buffer buf: K at sm + buf*8192 (4096 floats), V at +4096.

    const int head = blockIdx.x;
    const int qt = (gridDim.y - 1) - blockIdx.y;   // heavy first, chip-wide
    const int b = head >> 4, h = head & 15;
    const int tid = threadIdx.x, warp = tid >> 5, lane = tid & 31;
    const int gid = lane >> 2, tig = lane & 3;
    const int q0 = qt * 128;

    // Q fragments for this warp's 16 rows
    const float* qsrc = g_qp + ((size_t)head * 128 + qt * 8 + warp) * 1024;
    uint32_t qa[8][4];
#pragma unroll
    for (int kk = 0; kk < 8; kk++) {
        float4 t = *(const float4*)&qsrc[kk * 128 + lane * 4];
        qa[kk][0] = __float_as_uint(t.x); qa[kk][1] = __float_as_uint(t.y);
        qa[kk][2] = __float_as_uint(t.z); qa[kk][3] = __float_as_uint(t.w);
    }

    float O[8][4];
#pragma unroll
    for (int n = 0; n < 8; n++)
#pragma unroll
        for (int s = 0; s < 4; s++) O[n][s] = 0.f;
    float m_a = -1e30f, m_b = -1e30f, l_a = 0.f, l_b = 0.f;

    const int KTILES = 2 * qt + 2;
    const float* kbase = g_kp + (size_t)head * 131072;
    const float* vbase = g_vp + (size_t)head * 131072;

    // prologue: tile 0 -> buf 0 (two contiguous 16KB copies)
#pragma unroll
    for (int i = 0; i < 4; i++) {
        const int id = tid + i * 256;
        cp16(sb + id * 16, kbase + id * 4);
        cp16(sb + 16384 + id * 16, vbase + id * 4);
    }
    CP_COMMIT();

    for (int kt = 0; kt < KTILES; kt++) {
        const int buf = kt & 1;
        CP_WAIT0();
        __syncthreads();
        if (kt + 1 < KTILES) {
            const float* ks = kbase + (size_t)(kt + 1) * 4096;
            const float* vs = vbase + (size_t)(kt + 1) * 4096;
            const uint32_t db = sb + (1 - buf) * 32768;
#pragma unroll
            for (int i = 0; i < 4; i++) {
                const int id = tid + i * 256;
                cp16(db + id * 16, ks + id * 4);
                cp16(db + 16384 + id * 16, vs + id * 4);
            }
            CP_COMMIT();
        }

        const float* Ks = sm + buf * 8192;
        const float* Vs = sm + buf * 8192 + 4096;
        const int k0 = kt * 64;

        // S = Q @ K^T  (pair-packed: 32 LDS.128 for 64 mma)
        float S[8][4];
#pragma unroll
        for (int n = 0; n < 8; n++)
#pragma unroll
            for (int s = 0; s < 4; s++) S[n][s] = 0.f;
#pragma unroll
        for (int kk = 0; kk < 8; kk++) {
#pragma unroll
            for (int ntp = 0; ntp < 4; ntp++) {
                float4 t = *(const float4*)&Ks[((kk * 4 + ntp) * 32 + lane) * 4];
                mma_tf32(S[2 * ntp], qa[kk][0], qa[kk][1], qa[kk][2], qa[kk][3],
                         __float_as_uint(t.x), __float_as_uint(t.y));
                mma_tf32(S[2 * ntp + 1], qa[kk][0], qa[kk][1], qa[kk][2], qa[kk][3],
                         __float_as_uint(t.z), __float_as_uint(t.w));
            }
        }

        // causal mask (skip for fully-past tiles)
        if (k0 + 63 > q0 + warp * 16) {
#pragma unroll
            for (int nt = 0; nt < 8; nt++)
#pragma unroll
                for (int sl = 0; sl < 4; sl++) {
                    const int key = k0 + nt * 8 + tig * 2 + (sl & 1);
                    const int row = q0 + warp * 16 + gid + (sl >> 1) * 8;
                    if (key > row) S[nt][sl] = -1e30f;
                }
        }

        // online softmax (rows a: slots 0,1; rows b: slots 2,3)
        float mx_a = -1e30f, mx_b = -1e30f;
#pragma unroll
        for (int nt = 0; nt < 8; nt++) {
            mx_a = fmaxf(mx_a, fmaxf(S[nt][0], S[nt][1]));
            mx_b = fmaxf(mx_b, fmaxf(S[nt][2], S[nt][3]));
        }
        mx_a = fmaxf(mx_a, __shfl_xor_sync(0xffffffffu, mx_a, 1));
        mx_a = fmaxf(mx_a, __shfl_xor_sync(0xffffffffu, mx_a, 2));
        mx_b = fmaxf(mx_b, __shfl_xor_sync(0xffffffffu, mx_b, 1));
        mx_b = fmaxf(mx_b, __shfl_xor_sync(0xffffffffu, mx_b, 2));

        const float na = fmaxf(m_a, mx_a), nb = fmaxf(m_b, mx_b);
        const float ca = __expf(m_a - na), cb = __expf(m_b - nb);
        m_a = na; m_b = nb;

        float sa = 0.f, sbv = 0.f;
#pragma unroll
        for (int nt = 0; nt < 8; nt++) {
#pragma unroll
            for (int sl = 0; sl < 4; sl++) {
                const float p = __expf(S[nt][sl] - ((sl < 2) ? na : nb));
                const float ptf = f2tf32f(p);      // round before summing
                if (sl < 2) sa += ptf; else sbv += ptf;
                S[nt][sl] = ptf;                   // S now holds P (tf32)
            }
        }
        sa  += __shfl_xor_sync(0xffffffffu, sa, 1);
        sa  += __shfl_xor_sync(0xffffffffu, sa, 2);
        sbv += __shfl_xor_sync(0xffffffffu, sbv, 1);
        sbv += __shfl_xor_sync(0xffffffffu, sbv, 2);
        l_a = l_a * ca + sa;
        l_b = l_b * cb + sbv;
#pragma unroll
        for (int n = 0; n < 8; n++) {
            O[n][0] *= ca; O[n][1] *= ca; O[n][2] *= cb; O[n][3] *= cb;
        }

        // O += P @ V : shfl-transpose P (C-frag) -> A-frags; paired V LDS
        const int l0 = gid * 4 + (tig >> 1);
        const int l2 = l0 + 2;
        const bool odd = (tig & 1);
#pragma unroll
        for (int kk2 = 0; kk2 < 8; kk2++) {
            const float e00 = __shfl_sync(0xffffffffu, S[kk2][0], l0);
            const float e01 = __shfl_sync(0xffffffffu, S[kk2][1], l0);
            const float e10 = __shfl_sync(0xffffffffu, S[kk2][2], l0);
            const float e11 = __shfl_sync(0xffffffffu, S[kk2][3], l0);
            const float e20 = __shfl_sync(0xffffffffu, S[kk2][0], l2);
            const float e21 = __shfl_sync(0xffffffffu, S[kk2][1], l2);
            const float e30 = __shfl_sync(0xffffffffu, S[kk2][2], l2);
            const float e31 = __shfl_sync(0xffffffffu, S[kk2][3], l2);
            const uint32_t a0 = __float_as_uint(odd ? e01 : e00);
            const uint32_t a1 = __float_as_uint(odd ? e11 : e10);
            const uint32_t a2 = __float_as_uint(odd ? e21 : e20);
            const uint32_t a3 = __float_as_uint(odd ? e31 : e30);
#pragma unroll
            for (int ntp2 = 0; ntp2 < 4; ntp2++) {
                float4 t = *(const float4*)&Vs[((kk2 * 4 + ntp2) * 32 + lane) * 4];
                mma_tf32(O[2 * ntp2], a0, a1, a2, a3,
                         __float_as_uint(t.x), __float_as_uint(t.y));
                mma_tf32(O[2 * ntp2 + 1], a0, a1, a2, a3,
                         __float_as_uint(t.z), __float_as_uint(t.w));
            }
        }
    }

    // epilogue: normalize, write out[b, row, h*64 + col]
    const float inva = 1.f / l_a, invb = 1.f / l_b;
    const int ra = q0 + warp * 16 + gid;
    const int rb = ra + 8;
    float* oa = out + ((size_t)(b * SS + ra)) * DD + (size_t)h * 64;
    float* ob = out + ((size_t)(b * SS + rb)) * DD + (size_t)h * 64;
#pragma unroll
    for (int nt2 = 0; nt2 < 8; nt2++) {
        const int col = nt2 * 8 + tig * 2;
        float2 va, vb2;
        va.x  = O[nt2][0] * inva; va.y  = O[nt2][1] * inva;
        vb2.x = O[nt2][2] * invb; vb2.y = O[nt2][3] * invb;
        *(float2*)&oa[col] = va;
        *(float2*)&ob[col] = vb2;
    }
}

// ---------------------------------------------------------------------------
extern "C" void kernel_launch(void* const* d_in, const int* in_sizes, int n_in,
                              void* d_out, int out_size)
{
    const float* x   = (const float*)d_in[0];
    const float* Wqk = (const float*)d_in[1];
    const float* bqk = (const float*)d_in[2];
    const float* Wv  = (const float*)d_in[3];
    const float* bv  = (const float*)d_in[4];
    float* out = (float*)d_out;

    prep_x<<<4096, 256>>>(x);
    prep_w<<<3072, 256>>>(Wqk, Wv);

    cudaFuncSetAttribute(qkv_gemm, cudaFuncAttributeMaxDynamicSharedMemorySize, 65536);
    qkv_gemm<<<dim3(24, 32), 256, 65536>>>(bqk, bv);

    cudaFuncSetAttribute(attn_kernel, cudaFuncAttributeMaxDynamicSharedMemorySize, 65536);
    attn_kernel<<<dim3(32, 16), 256, 65536>>>(out);
}

// round 10
// speedup vs baseline: 6.7381x; 1.0220x over previous
#include <cuda_runtime.h>
#include <cstdint>

#define BB 2
#define SS 2048
#define DD 1024
#define HH 16
#define NQK 2048
#define NTOT 3072

// tf32 fragment-permuted scratch (all values pre-rounded to tf32):
// g_x4 : x as A-frags        [mtg(256)][kkg(128)][lane(32)][slot(4)]
// g_w  : W as PAIRED B-frags [ntpg(192)][kkg(128)][lane(32)][4]
// g_qp : q as A-frags        [head(32)][rg(128)][kk(8)][lane(32)][slot(4)] (q pre-scaled 1/8)
// g_kp : k as PAIRED B-frags [head(32)][tile(32)][kk(8)][ntp(4)][lane(32)][4] (n=key,k=dh)
// g_vp : v as PAIRED B-frags [head(32)][tile(32)][kk2(8)][ntp2(4)][lane(32)][4] (k=key,n=dh)
__device__ float g_x4[4194304];
__device__ float g_w [3145728];
__device__ float g_qp[4194304];
__device__ float g_kp[4194304];
__device__ float g_vp[4194304];

// ---------------------------------------------------------------------------
__device__ __forceinline__ uint32_t f2tf32(float x) {
    uint32_t r; asm("cvt.rna.tf32.f32 %0, %1;" : "=r"(r) : "f"(x)); return r;
}
__device__ __forceinline__ float f2tf32f(float x) { return __uint_as_float(f2tf32(x)); }

__device__ __forceinline__ void mma_tf32(float c[4],
                                         uint32_t a0, uint32_t a1, uint32_t a2, uint32_t a3,
                                         uint32_t b0, uint32_t b1) {
    asm volatile(
        "mma.sync.aligned.m16n8k8.row.col.f32.tf32.tf32.f32 "
        "{%0,%1,%2,%3}, {%4,%5,%6,%7}, {%8,%9}, {%0,%1,%2,%3};"
        : "+f"(c[0]), "+f"(c[1]), "+f"(c[2]), "+f"(c[3])
        : "r"(a0), "r"(a1), "r"(a2), "r"(a3), "r"(b0), "r"(b1));
}

__device__ __forceinline__ void cp16(uint32_t dst, const void* src) {
    asm volatile("cp.async.cg.shared.global [%0], [%1], 16;" :: "r"(dst), "l"(src));
}
#define CP_COMMIT() asm volatile("cp.async.commit_group;" ::: "memory")
#define CP_WAIT0()  asm volatile("cp.async.wait_group 0;" ::: "memory")

// ---------------------------------------------------------------------------
// Prepass: x -> A-frag tf32 layout.
// ---------------------------------------------------------------------------
__global__ __launch_bounds__(256) void prep_x(const float* __restrict__ x)
{
    const int g = blockIdx.x * 256 + threadIdx.x;
    const int lane = g & 31, c = g >> 5;            // chunk 0..32767
    const int kkg = c & 127, mtg = c >> 7;
    float4 o;
    float* po = (float*)&o;
#pragma unroll
    for (int sl = 0; sl < 4; sl++) {
        const int ir = (lane >> 2) + (sl & 1) * 8;
        const int cc = (lane & 3) + (sl >> 1) * 4;
        po[sl] = f2tf32f(x[(size_t)(mtg * 16 + ir) * DD + kkg * 8 + cc]);
    }
    *(float4*)&g_x4[(size_t)c * 128 + lane * 4] = o;
}

// Prepass: [Wqk|Wv] -> pair-packed B-frag tf32 layout.
__global__ __launch_bounds__(256) void prep_w(const float* __restrict__ Wqk,
                                              const float* __restrict__ Wv)
{
    const int g = blockIdx.x * 256 + threadIdx.x;   // 0..786431
    const int lane = g & 31, c = g >> 5;            // chunk 0..24575
    const int kkg = c & 127, ntpg = c >> 7;         // ntpg 0..191
    float4 o;
    float* po = (float*)&o;
#pragma unroll
    for (int sub = 0; sub < 4; sub++) {
        const int pnt = sub >> 1, sl = sub & 1;
        const int n = (ntpg * 2 + pnt) * 8 + (lane >> 2);
        const int k = kkg * 8 + (lane & 3) + sl * 4;
        const float* W; int ldw, col;
        if (n < NQK) { W = Wqk; ldw = NQK; col = n; }
        else         { W = Wv;  ldw = DD;  col = n - NQK; }
        po[sub] = f2tf32f(W[(size_t)k * ldw + col]);
    }
    *(float4*)&g_w[(size_t)c * 128 + lane * 4] = o;
}

// ---------------------------------------------------------------------------
// QKV GEMM: 128x128 block tile, k-step 32, cp.async double-buffered.
// 4 warps, 64x64 warp tile: per kk 8 LDS.128 feed 32 mma.
// ---------------------------------------------------------------------------
__global__ __launch_bounds__(128, 2) void qkv_gemm(const float* __restrict__ bqk,
                                                   const float* __restrict__ bv)
{
    extern __shared__ float sm[];
    const uint32_t sb = (uint32_t)__cvta_generic_to_shared(sm);
    // As(buf) = sm + buf*4096; Bs(buf) = sm + 8192 + buf*4096 (floats).

    const int bm = blockIdx.y, bn = blockIdx.x;
    const int n0 = bn * 128;
    const int tid = threadIdx.x, warp = tid >> 5, lane = tid & 31;
    const int wm = warp >> 1, wn = warp & 1;      // 2 x 2 warp grid, 64x64 each
    const int gid = lane >> 2, tig = lane & 3;

    float c[4][8][4];
#pragma unroll
    for (int i = 0; i < 4; i++)
#pragma unroll
        for (int j = 0; j < 8; j++)
#pragma unroll
            for (int s = 0; s < 4; s++) c[i][j][s] = 0.f;

    auto load_tile = [&](int it, int buf) {
        const int kkg0 = it * 4;
#pragma unroll
        for (int i = 0; i < 8; i++) {       // A: 32 chunks x 512B
            const int id = tid + i * 128;
            const int chunk = id >> 5, off = id & 31;
            const int kk = chunk >> 3, mt = chunk & 7;
            const float* src = &g_x4[((size_t)(bm * 8 + mt) * 128 + kkg0 + kk) * 128 + off * 4];
            cp16(sb + (buf * 4096 + chunk * 128 + off * 4) * 4, src);
        }
#pragma unroll
        for (int i = 0; i < 8; i++) {       // B: 32 chunks x 512B (paired)
            const int id = tid + i * 128;
            const int chunk = id >> 5, off = id & 31;
            const int kk = chunk >> 3, ntp = chunk & 7;
            const float* src = &g_w[((size_t)(bn * 8 + ntp) * 128 + kkg0 + kk) * 128 + off * 4];
            cp16(sb + (8192 + buf * 4096 + chunk * 128 + off * 4) * 4, src);
        }
    };

    load_tile(0, 0);
    CP_COMMIT();

    for (int it = 0; it < 32; it++) {
        const int buf = it & 1;
        CP_WAIT0();
        __syncthreads();
        if (it + 1 < 32) { load_tile(it + 1, 1 - buf); CP_COMMIT(); }

        const float* As = sm + buf * 4096;
        const float* Bs = sm + 8192 + buf * 4096;
#pragma unroll
        for (int kk = 0; kk < 4; kk++) {
            uint32_t af[4][4], bf[8][2];
#pragma unroll
            for (int mt = 0; mt < 4; mt++) {
                float4 t = *(const float4*)&As[(((kk << 3) + (wm * 4 + mt)) * 32 + lane) * 4];
                af[mt][0] = __float_as_uint(t.x); af[mt][1] = __float_as_uint(t.y);
                af[mt][2] = __float_as_uint(t.z); af[mt][3] = __float_as_uint(t.w);
            }
#pragma unroll
            for (int ntpi = 0; ntpi < 4; ntpi++) {   // paired: 4 LDS.128 -> 8 frags
                float4 t = *(const float4*)&Bs[(((kk << 3) + (wn * 4 + ntpi)) * 32 + lane) * 4];
                bf[2 * ntpi][0]     = __float_as_uint(t.x);
                bf[2 * ntpi][1]     = __float_as_uint(t.y);
                bf[2 * ntpi + 1][0] = __float_as_uint(t.z);
                bf[2 * ntpi + 1][1] = __float_as_uint(t.w);
            }
#pragma unroll
            for (int mt = 0; mt < 4; mt++)
#pragma unroll
                for (int nt = 0; nt < 8; nt++)
                    mma_tf32(c[mt][nt], af[mt][0], af[mt][1], af[mt][2], af[mt][3],
                             bf[nt][0], bf[nt][1]);
        }
    }

    // Epilogue: bias, q-scale, tf32-round, scatter to fragment-permuted q/k/v
    const int typ = (n0 < DD) ? 0 : (n0 < NQK ? 1 : 2);
    const float* bias = (typ == 2) ? bv : bqk;
    const int bcol0 = (typ == 2) ? (n0 - NQK) : n0;
    const int nnbase = (typ == 0) ? n0 : (typ == 1 ? n0 - DD : n0 - NQK);

#pragma unroll
    for (int nt = 0; nt < 8; nt++) {
        const int ncl = wn * 64 + nt * 8 + tig * 2;
        const float b0 = bias[bcol0 + ncl];
        const float b1 = bias[bcol0 + ncl + 1];
        const int nn = nnbase + ncl;
        const int h = nn >> 6;
        const int d0 = nn & 63;      // even
#pragma unroll
        for (int mt = 0; mt < 4; mt++) {
#pragma unroll
            for (int half = 0; half < 2; half++) {
                const int m = bm * 128 + wm * 64 + mt * 16 + gid + half * 8;
                const int bb = m >> 11, s = m & (SS - 1);
                const int head = bb * HH + h;
                float v0 = c[mt][nt][half * 2 + 0] + b0;
                float v1 = c[mt][nt][half * 2 + 1] + b1;
                if (typ == 0) {
                    v0 *= 0.125f; v1 *= 0.125f;
                    const int rg = s >> 4, ir = s & 15;
                    const int kk = d0 >> 3;
                    const int cc0 = d0 & 7, cc1 = cc0 + 1;
                    const int lnb = (ir & 7) * 4;
                    const int slb = ir >> 3;
                    const size_t base = (((size_t)head * 128 + rg) * 8 + kk) * 128;
                    g_qp[base + (lnb + (cc0 & 3)) * 4 + slb + ((cc0 >> 2) << 1)] = f2tf32f(v0);
                    g_qp[base + (lnb + (cc1 & 3)) * 4 + slb + ((cc1 >> 2) << 1)] = f2tf32f(v1);
                } else if (typ == 1) {
                    // K pair-packed: [head][tile][kk][ntp][lane][4]
                    const int tile = s >> 6, j = s & 63;
                    const int ntp = j >> 4, pnt = (j >> 3) & 1, nc = j & 7;
                    const int kk = d0 >> 3;
                    const int kr0 = d0 & 7, kr1 = kr0 + 1;   // kr0 even
                    const size_t base = ((((size_t)head * 32 + tile) * 8 + kk) * 4 + ntp) * 128;
                    g_kp[base + (nc * 4 + (kr0 & 3)) * 4 + pnt * 2 + (kr0 >> 2)] = f2tf32f(v0);
                    g_kp[base + (nc * 4 + (kr1 & 3)) * 4 + pnt * 2 + (kr1 >> 2)] = f2tf32f(v1);
                } else {
                    // V pair-packed: [head][tile][kk2][ntp2][lane][4]
                    const int tile = s >> 6, j = s & 63;
                    const int kk2 = j >> 3, kr = j & 7;
                    const int ntp2 = d0 >> 4, pnt2 = (d0 >> 3) & 1;
                    const int nc0 = d0 & 7, nc1 = nc0 + 1;
                    const int sub = pnt2 * 2 + (kr >> 2);
                    const size_t base = ((((size_t)head * 32 + tile) * 8 + kk2) * 4 + ntp2) * 128;
                    g_vp[base + (nc0 * 4 + (kr & 3)) * 4 + sub] = f2tf32f(v0);
                    g_vp[base + (nc1 * 4 + (kr & 3)) * 4 + sub] = f2tf32f(v1);
                }
            }
        }
    }
}

// ---------------------------------------------------------------------------
// Causal flash attention: 128 q rows/block, 4 warps x 32 rows (2 A-frag sets).
// K/V fragment LDS shared across both 16-row sub-tiles -> half the smem
// traffic per mma vs 16-row warps. Double-buffered bulk cp.async KV tiles.
// ---------------------------------------------------------------------------
__global__ __launch_bounds__(128, 2) void attn_kernel(float* __restrict__ out)
{
    extern __shared__ float sm[];
    const uint32_t sb = (uint32_t)__cvta_generic_to_shared(sm);
    // buffer buf: K at sm + buf*8192 (4096 floats), V at +4096.

    const int head = blockIdx.x;
    const int qt = (gridDim.y - 1) - blockIdx.y;   // heavy first, chip-wide
    const int b = head >> 4, h = head & 15;
    const int tid = threadIdx.x, warp = tid >> 5, lane = tid & 31;
    const int gid = lane >> 2, tig = lane & 3;
    const int q0 = qt * 128;

    // Q fragments for this warp's 32 rows (two 16-row groups)
    uint32_t qa[2][8][4];
#pragma unroll
    for (int mt = 0; mt < 2; mt++) {
        const float* qsrc = g_qp + ((size_t)head * 128 + qt * 8 + warp * 2 + mt) * 1024;
#pragma unroll
        for (int kk = 0; kk < 8; kk++) {
            float4 t = *(const float4*)&qsrc[kk * 128 + lane * 4];
            qa[mt][kk][0] = __float_as_uint(t.x); qa[mt][kk][1] = __float_as_uint(t.y);
            qa[mt][kk][2] = __float_as_uint(t.z); qa[mt][kk][3] = __float_as_uint(t.w);
        }
    }

    float O[2][8][4];
#pragma unroll
    for (int mt = 0; mt < 2; mt++)
#pragma unroll
        for (int n = 0; n < 8; n++)
#pragma unroll
            for (int s = 0; s < 4; s++) O[mt][n][s] = 0.f;
    float m_[2][2], l_[2][2];
#pragma unroll
    for (int mt = 0; mt < 2; mt++) { m_[mt][0] = m_[mt][1] = -1e30f; l_[mt][0] = l_[mt][1] = 0.f; }

    const int KTILES = 2 * qt + 2;
    const float* kbase = g_kp + (size_t)head * 131072;
    const float* vbase = g_vp + (size_t)head * 131072;

    // prologue: tile 0 -> buf 0
#pragma unroll
    for (int i = 0; i < 8; i++) {
        const int id = tid + i * 128;
        cp16(sb + id * 16, kbase + id * 4);
        cp16(sb + 16384 + id * 16, vbase + id * 4);
    }
    CP_COMMIT();

    for (int kt = 0; kt < KTILES; kt++) {
        const int buf = kt & 1;
        CP_WAIT0();
        __syncthreads();
        if (kt + 1 < KTILES) {
            const float* ks = kbase + (size_t)(kt + 1) * 4096;
            const float* vs = vbase + (size_t)(kt + 1) * 4096;
            const uint32_t db = sb + (1 - buf) * 32768;
#pragma unroll
            for (int i = 0; i < 8; i++) {
                const int id = tid + i * 128;
                cp16(db + id * 16, ks + id * 4);
                cp16(db + 16384 + id * 16, vs + id * 4);
            }
            CP_COMMIT();
        }

        const float* Ks = sm + buf * 8192;
        const float* Vs = sm + buf * 8192 + 4096;
        const int k0 = kt * 64;

        // S = Q @ K^T : each K frag LDS.128 feeds 4 mma (2 pair x 2 mt)
        float S[2][8][4];
#pragma unroll
        for (int mt = 0; mt < 2; mt++)
#pragma unroll
            for (int n = 0; n < 8; n++)
#pragma unroll
                for (int s = 0; s < 4; s++) S[mt][n][s] = 0.f;
#pragma unroll
        for (int kk = 0; kk < 8; kk++) {
#pragma unroll
            for (int ntp = 0; ntp < 4; ntp++) {
                float4 t = *(const float4*)&Ks[((kk * 4 + ntp) * 32 + lane) * 4];
                const uint32_t b0 = __float_as_uint(t.x), b1 = __float_as_uint(t.y);
                const uint32_t b2 = __float_as_uint(t.z), b3 = __float_as_uint(t.w);
#pragma unroll
                for (int mt = 0; mt < 2; mt++) {
                    mma_tf32(S[mt][2 * ntp], qa[mt][kk][0], qa[mt][kk][1],
                             qa[mt][kk][2], qa[mt][kk][3], b0, b1);
                    mma_tf32(S[mt][2 * ntp + 1], qa[mt][kk][0], qa[mt][kk][1],
                             qa[mt][kk][2], qa[mt][kk][3], b2, b3);
                }
            }
        }

        // causal mask + online softmax per 16-row sub-tile
#pragma unroll
        for (int mt = 0; mt < 2; mt++) {
            const int rbase = q0 + warp * 32 + mt * 16;
            if (k0 + 63 > rbase) {
#pragma unroll
                for (int nt = 0; nt < 8; nt++)
#pragma unroll
                    for (int sl = 0; sl < 4; sl++) {
                        const int key = k0 + nt * 8 + tig * 2 + (sl & 1);
                        const int row = rbase + gid + (sl >> 1) * 8;
                        if (key > row) S[mt][nt][sl] = -1e30f;
                    }
            }

            float mx_a = -1e30f, mx_b = -1e30f;
#pragma unroll
            for (int nt = 0; nt < 8; nt++) {
                mx_a = fmaxf(mx_a, fmaxf(S[mt][nt][0], S[mt][nt][1]));
                mx_b = fmaxf(mx_b, fmaxf(S[mt][nt][2], S[mt][nt][3]));
            }
            mx_a = fmaxf(mx_a, __shfl_xor_sync(0xffffffffu, mx_a, 1));
            mx_a = fmaxf(mx_a, __shfl_xor_sync(0xffffffffu, mx_a, 2));
            mx_b = fmaxf(mx_b, __shfl_xor_sync(0xffffffffu, mx_b, 1));
            mx_b = fmaxf(mx_b, __shfl_xor_sync(0xffffffffu, mx_b, 2));

            const float na = fmaxf(m_[mt][0], mx_a), nb = fmaxf(m_[mt][1], mx_b);
            const float ca = __expf(m_[mt][0] - na), cb = __expf(m_[mt][1] - nb);
            m_[mt][0] = na; m_[mt][1] = nb;

            float sa = 0.f, sbv = 0.f;
#pragma unroll
            for (int nt = 0; nt < 8; nt++) {
#pragma unroll
                for (int sl = 0; sl < 4; sl++) {
                    const float p = __expf(S[mt][nt][sl] - ((sl < 2) ? na : nb));
                    const float ptf = f2tf32f(p);      // round before summing
                    if (sl < 2) sa += ptf; else sbv += ptf;
                    S[mt][nt][sl] = ptf;               // S now holds P (tf32)
                }
            }
            sa  += __shfl_xor_sync(0xffffffffu, sa, 1);
            sa  += __shfl_xor_sync(0xffffffffu, sa, 2);
            sbv += __shfl_xor_sync(0xffffffffu, sbv, 1);
            sbv += __shfl_xor_sync(0xffffffffu, sbv, 2);
            l_[mt][0] = l_[mt][0] * ca + sa;
            l_[mt][1] = l_[mt][1] * cb + sbv;
#pragma unroll
            for (int n = 0; n < 8; n++) {
                O[mt][n][0] *= ca; O[mt][n][1] *= ca;
                O[mt][n][2] *= cb; O[mt][n][3] *= cb;
            }
        }

        // O += P @ V : V frags loaded once per kk2, shared across both mt
        const int l0 = gid * 4 + (tig >> 1);
        const int l2 = l0 + 2;
        const bool odd = (tig & 1);
#pragma unroll
        for (int kk2 = 0; kk2 < 8; kk2++) {
            float4 v[4];
#pragma unroll
            for (int ntp2 = 0; ntp2 < 4; ntp2++)
                v[ntp2] = *(const float4*)&Vs[((kk2 * 4 + ntp2) * 32 + lane) * 4];
#pragma unroll
            for (int mt = 0; mt < 2; mt++) {
                const float e00 = __shfl_sync(0xffffffffu, S[mt][kk2][0], l0);
                const float e01 = __shfl_sync(0xffffffffu, S[mt][kk2][1], l0);
                const float e10 = __shfl_sync(0xffffffffu, S[mt][kk2][2], l0);
                const float e11 = __shfl_sync(0xffffffffu, S[mt][kk2][3], l0);
                const float e20 = __shfl_sync(0xffffffffu, S[mt][kk2][0], l2);
                const float e21 = __shfl_sync(0xffffffffu, S[mt][kk2][1], l2);
                const float e30 = __shfl_sync(0xffffffffu, S[mt][kk2][2], l2);
                const float e31 = __shfl_sync(0xffffffffu, S[mt][kk2][3], l2);
                const uint32_t a0 = __float_as_uint(odd ? e01 : e00);
                const uint32_t a1 = __float_as_uint(odd ? e11 : e10);
                const uint32_t a2 = __float_as_uint(odd ? e21 : e20);
                const uint32_t a3 = __float_as_uint(odd ? e31 : e30);
#pragma unroll
                for (int ntp2 = 0; ntp2 < 4; ntp2++) {
                    mma_tf32(O[mt][2 * ntp2], a0, a1, a2, a3,
                             __float_as_uint(v[ntp2].x), __float_as_uint(v[ntp2].y));
                    mma_tf32(O[mt][2 * ntp2 + 1], a0, a1, a2, a3,
                             __float_as_uint(v[ntp2].z), __float_as_uint(v[ntp2].w));
                }
            }
        }
    }

    // epilogue: normalize, write out[b, row, h*64 + col]
#pragma unroll
    for (int mt = 0; mt < 2; mt++) {
        const float inva = 1.f / l_[mt][0], invb = 1.f / l_[mt][1];
        const int ra = q0 + warp * 32 + mt * 16 + gid;
        const int rb = ra + 8;
        float* oa = out + ((size_t)(b * SS + ra)) * DD + (size_t)h * 64;
        float* ob = out + ((size_t)(b * SS + rb)) * DD + (size_t)h * 64;
#pragma unroll
        for (int nt2 = 0; nt2 < 8; nt2++) {
            const int col = nt2 * 8 + tig * 2;
            float2 va, vb2;
            va.x  = O[mt][nt2][0] * inva; va.y  = O[mt][nt2][1] * inva;
            vb2.x = O[mt][nt2][2] * invb; vb2.y = O[mt][nt2][3] * invb;
            *(float2*)&oa[col] = va;
            *(float2*)&ob[col] = vb2;
        }
    }
}

// ---------------------------------------------------------------------------
extern "C" void kernel_launch(void* const* d_in, const int* in_sizes, int n_in,
                              void* d_out, int out_size)
{
    const float* x   = (const float*)d_in[0];
    const float* Wqk = (const float*)d_in[1];
    const float* bqk = (const float*)d_in[2];
    const float* Wv  = (const float*)d_in[3];
    const float* bv  = (const float*)d_in[4];
    float* out = (float*)d_out;

    prep_x<<<4096, 256>>>(x);
    prep_w<<<3072, 256>>>(Wqk, Wv);

    cudaFuncSetAttribute(qkv_gemm, cudaFuncAttributeMaxDynamicSharedMemorySize, 65536);
    qkv_gemm<<<dim3(24, 32), 128, 65536>>>(bqk, bv);

    cudaFuncSetAttribute(attn_kernel, cudaFuncAttributeMaxDynamicSharedMemorySize, 65536);
    attn_kernel<<<dim3(32, 16), 128, 65536>>>(out);
}